// round 14
// baseline (speedup 1.0000x reference)
#include <cuda_runtime.h>
#include <cuda_fp16.h>
#include <math.h>

#define NN 100000
#define EE 1000000
#define DH 64
#define DIN 128
#define DOUT 40
#define LL 7
#define GBLK 1563      // ceil(NN/64)
#define SCB 391        // ceil(NN/256)
#define EB  3907       // ceil(EE/256)
#define MB  12500      // NN*32/256
#define LD 68          // padded smem row stride (floats)

// per-lane message packet: e = exp(m), m = relu(aff(h))+eps  (two features each)
struct __align__(8) Msg { __half2 e; __half2 m; };

// ---------------- scratch (static device memory; no allocs) ----------------
__device__ float    g_bufA[(size_t)NN * DH];
__device__ float    g_bufB[(size_t)NN * DH];
__device__ float    g_bufU[(size_t)NN * DH];
__device__ Msg      g_msg[(size_t)NN * 32];
__device__ int      g_counts[NN];
__device__ int      g_row_off[NN + 1];
__device__ int      g_cursor[NN];
__device__ int      g_csr_src[EE];
__device__ float    g_psum[GBLK][DH];
__device__ float    g_psq[GBLK][DH];
__device__ float    g_aff_a[DH];
__device__ float    g_aff_b[DH];
__device__ unsigned g_done = 0;
// decoupled-lookback scan state: high 32 bits status (0=invalid,1=agg,2=prefix), low 32 value
__device__ unsigned long long g_state[SCB];

// ---------------- fused: encoder GEMM + CSR count ----------------
__global__ void enccount_kernel(const float* __restrict__ in,
                                const float* __restrict__ W,
                                const float* __restrict__ bias,
                                float* __restrict__ out,
                                const int* __restrict__ dstp) {
    __shared__ float sIn[64 * LD];
    __shared__ float sW[64 * LD];
    if (blockIdx.x >= GBLK) {
        int i = (blockIdx.x - GBLK) * 256 + threadIdx.x;
        if (i < EE) atomicAdd(&g_counts[dstp[i]], 1);
        return;
    }
    const int row0 = blockIdx.x * 64;
    const int tx = threadIdx.x & 15;
    const int ty = threadIdx.x >> 4;

    float acc[4][4];
#pragma unroll
    for (int i = 0; i < 4; i++)
#pragma unroll
        for (int j = 0; j < 4; j++) acc[i][j] = 0.f;

    for (int kc = 0; kc < DIN; kc += 64) {
#pragma unroll
        for (int i = threadIdx.x; i < 1024; i += 256) {
            int r = i >> 4, c4 = i & 15;
            int grow = row0 + r;
            float4 v = make_float4(0.f, 0.f, 0.f, 0.f);
            if (grow < NN) v = *(const float4*)&in[(size_t)grow * DIN + kc + c4 * 4];
            *(float4*)&sIn[r * LD + c4 * 4] = v;
            *(float4*)&sW[r * LD + c4 * 4] = *(const float4*)&W[(size_t)(kc + r) * 64 + c4 * 4];
        }
        __syncthreads();
#pragma unroll
        for (int k = 0; k < 64; k++) {
            float4 wv = *(const float4*)&sW[k * LD + tx * 4];
            float x0 = sIn[(ty * 4 + 0) * LD + k];
            float x1 = sIn[(ty * 4 + 1) * LD + k];
            float x2 = sIn[(ty * 4 + 2) * LD + k];
            float x3 = sIn[(ty * 4 + 3) * LD + k];
            acc[0][0] = fmaf(x0, wv.x, acc[0][0]); acc[0][1] = fmaf(x0, wv.y, acc[0][1]);
            acc[0][2] = fmaf(x0, wv.z, acc[0][2]); acc[0][3] = fmaf(x0, wv.w, acc[0][3]);
            acc[1][0] = fmaf(x1, wv.x, acc[1][0]); acc[1][1] = fmaf(x1, wv.y, acc[1][1]);
            acc[1][2] = fmaf(x1, wv.z, acc[1][2]); acc[1][3] = fmaf(x1, wv.w, acc[1][3]);
            acc[2][0] = fmaf(x2, wv.x, acc[2][0]); acc[2][1] = fmaf(x2, wv.y, acc[2][1]);
            acc[2][2] = fmaf(x2, wv.z, acc[2][2]); acc[2][3] = fmaf(x2, wv.w, acc[2][3]);
            acc[3][0] = fmaf(x3, wv.x, acc[3][0]); acc[3][1] = fmaf(x3, wv.y, acc[3][1]);
            acc[3][2] = fmaf(x3, wv.z, acc[3][2]); acc[3][3] = fmaf(x3, wv.w, acc[3][3]);
        }
        __syncthreads();
    }

    float4 bv = *(const float4*)&bias[tx * 4];
#pragma unroll
    for (int r = 0; r < 4; r++) {
        int grow = row0 + ty * 4 + r;
        if (grow < NN) {
            float4 o;
            o.x = acc[r][0] + bv.x; o.y = acc[r][1] + bv.y;
            o.z = acc[r][2] + bv.z; o.w = acc[r][3] + bv.w;
            *(float4*)&out[(size_t)grow * 64 + tx * 4] = o;
        }
    }
}

// ---------------- single-pass decoupled-lookback scan ----------------
__global__ void scan1_kernel() {
    __shared__ int s[256];
    __shared__ int s_ex;
    const int b = blockIdx.x;
    const int tid = threadIdx.x;
    const int i = b * 256 + tid;
    int v = (i < NN) ? g_counts[i] : 0;
    s[tid] = v;
    __syncthreads();
#pragma unroll
    for (int d = 1; d < 256; d <<= 1) {
        int u = (tid >= d) ? s[tid - d] : 0;
        __syncthreads();
        s[tid] += u;
        __syncthreads();
    }
    int incl = s[tid];            // inclusive local prefix
    int total = s[255];

    if (tid == 0) {
        volatile unsigned long long* st = (volatile unsigned long long*)g_state;
        int ex = 0;
        if (b == 0) {
            __threadfence();
            st[0] = (2ULL << 32) | (unsigned)total;
        } else {
            __threadfence();
            st[b] = (1ULL << 32) | (unsigned)total;
            int j = b - 1;
            while (true) {
                unsigned long long q = st[j];
                unsigned status = (unsigned)(q >> 32);
                if (status == 2u) { ex += (int)(q & 0xffffffffu); break; }
                if (status == 1u) { ex += (int)(q & 0xffffffffu); j--; }
            }
            __threadfence();
            st[b] = (2ULL << 32) | (unsigned)(ex + total);
        }
        s_ex = ex;
    }
    __syncthreads();
    int base = s_ex;
    if (i < NN) {
        int off = base + incl - v;   // exclusive
        g_row_off[i] = off;
        g_cursor[i]  = off;
        g_counts[i]  = 0;            // ready for next replay
    }
    if (b == SCB - 1 && tid == 255) g_row_off[NN] = base + incl;
}

// ---- msg body: m = relu(aff(h)) + eps ; e = exp(m); both fp16 ----
__device__ __forceinline__ void msg_body(int i, const float* __restrict__ h, int use_aff) {
    int f = (i & 31) * 2;
    float a0 = 1.f, a1 = 1.f, b0 = 0.f, b1 = 0.f;
    if (use_aff) {
        a0 = g_aff_a[f]; a1 = g_aff_a[f + 1];
        b0 = g_aff_b[f]; b1 = g_aff_b[f + 1];
    }
    float2 v = ((const float2*)h)[i];
    float m0 = fmaxf(fmaf(a0, v.x, b0), 0.f) + 1e-7f;
    float m1 = fmaxf(fmaf(a1, v.y, b1), 0.f) + 1e-7f;
    Msg pk;
    pk.e = __floats2half2_rn(__expf(m0), __expf(m1));
    pk.m = __floats2half2_rn(m0, m1);
    g_msg[i] = pk;
}

// ---------------- fused: CSR fill + layer-0 msg build (+ scan state reset) ----------------
__global__ void fillmsg_kernel(const int* __restrict__ srcp,
                               const int* __restrict__ dstp,
                               const float* __restrict__ h) {
    if (blockIdx.x < EB) {
        if (blockIdx.x == 0) {
            for (int j = threadIdx.x; j < SCB; j += 256) g_state[j] = 0ULL;
        }
        int i = blockIdx.x * 256 + threadIdx.x;
        if (i < EE) {
            int d = dstp[i];
            int pos = atomicAdd(&g_cursor[d], 1);
            g_csr_src[pos] = srcp[i];
        }
    } else {
        int i = (blockIdx.x - EB) * 256 + threadIdx.x;
        if (i < NN * 32) msg_body(i, h, 0);
    }
}

__global__ void msg_build_kernel(const float* __restrict__ h, int use_aff) {
    int i = blockIdx.x * blockDim.x + threadIdx.x;
    if (i < NN * 32) msg_body(i, h, use_aff);
}

// ---- one 4-edge gather batch: half2 in-batch accumulate, fp32 flush ----
__device__ __forceinline__ void batch4(int e, int lane,
                                       float& s0, float& s1, float& w0, float& w1) {
    int i0 = g_csr_src[e];
    int i1 = g_csr_src[e + 1];
    int i2 = g_csr_src[e + 2];
    int i3 = g_csr_src[e + 3];
    Msg p0 = g_msg[i0 * 32 + lane];
    Msg p1 = g_msg[i1 * 32 + lane];
    Msg p2 = g_msg[i2 * 32 + lane];
    Msg p3 = g_msg[i3 * 32 + lane];
    __half2 se = __hadd2(__hadd2(p0.e, p1.e), __hadd2(p2.e, p3.e));
    __half2 sw = __hfma2(p0.e, p0.m,
                 __hfma2(p1.e, p1.m,
                 __hfma2(p2.e, p2.m, __hmul2(p3.e, p3.m))));
    float2 fe = __half22float2(se);
    float2 fw = __half22float2(sw);
    s0 += fe.x; s1 += fe.y;
    w0 += fw.x; w1 += fw.y;
}

__device__ __forceinline__ void batch1(int e, int lane,
                                       float& s0, float& s1, float& w0, float& w1) {
    int i0 = g_csr_src[e];
    Msg p0 = g_msg[i0 * 32 + lane];
    float2 e0 = __half22float2(p0.e), m0 = __half22float2(p0.m);
    s0 += e0.x; s1 += e0.y;
    w0 = fmaf(e0.x, m0.x, w0);
    w1 = fmaf(e0.y, m0.y, w1);
}

// ---------------- GENConv aggregation: two nodes per warp, interleaved ----------------
__global__ void agg_kernel(const float* __restrict__ h,
                           float* __restrict__ u,
                           int use_aff) {
    int gw   = (blockIdx.x * blockDim.x + threadIdx.x) >> 5;
    int lane = threadIdx.x & 31;
    int n0 = gw * 2;
    if (n0 >= NN) return;
    int n1 = n0 + 1;
    int f = lane * 2;

    int p0 = g_row_off[n0], e0 = g_row_off[n0 + 1];
    int p1 = e0,            e1 = g_row_off[n1 + 1];

    float sA0 = 0.f, sA1 = 0.f, wA0 = 0.f, wA1 = 0.f;
    float sB0 = 0.f, sB1 = 0.f, wB0 = 0.f, wB1 = 0.f;

    while (p0 + 4 <= e0 && p1 + 4 <= e1) {
        batch4(p0, lane, sA0, sA1, wA0, wA1);
        batch4(p1, lane, sB0, sB1, wB0, wB1);
        p0 += 4; p1 += 4;
    }
    while (p0 + 4 <= e0) { batch4(p0, lane, sA0, sA1, wA0, wA1); p0 += 4; }
    while (p1 + 4 <= e1) { batch4(p1, lane, sB0, sB1, wB0, wB1); p1 += 4; }
    for (; p0 < e0; p0++) batch1(p0, lane, sA0, sA1, wA0, wA1);
    for (; p1 < e1; p1++) batch1(p1, lane, sB0, sB1, wB0, wB1);

    float a0 = 1.f, a1 = 1.f, b0 = 0.f, b1 = 0.f;
    if (use_aff) {
        a0 = g_aff_a[f]; a1 = g_aff_a[f + 1];
        b0 = g_aff_b[f]; b1 = g_aff_b[f + 1];
    }
    {
        float2 hn = *(const float2*)&h[(size_t)n0 * DH + f];
        float base0, base1;
        if (use_aff) {
            base0 = fmaxf(fmaf(a0, hn.x, b0), 0.f);
            base1 = fmaxf(fmaf(a1, hn.y, b1), 0.f);
        } else { base0 = hn.x; base1 = hn.y; }
        float2 o;
        o.x = base0 + ((sA0 > 0.f) ? wA0 / sA0 : 0.f);
        o.y = base1 + ((sA1 > 0.f) ? wA1 / sA1 : 0.f);
        *(float2*)&u[(size_t)n0 * DH + f] = o;
    }
    {
        float2 hn = *(const float2*)&h[(size_t)n1 * DH + f];
        float base0, base1;
        if (use_aff) {
            base0 = fmaxf(fmaf(a0, hn.x, b0), 0.f);
            base1 = fmaxf(fmaf(a1, hn.y, b1), 0.f);
        } else { base0 = hn.x; base1 = hn.y; }
        float2 o;
        o.x = base0 + ((sB0 > 0.f) ? wB0 / sB0 : 0.f);
        o.y = base1 + ((sB1 > 0.f) ? wB1 / sB1 : 0.f);
        *(float2*)&u[(size_t)n1 * DH + f] = o;
    }
}

// ---- tiled GEMM + stats + last-block BN finalize ----
template <bool RES, bool STATS>
__global__ void gemm_kernel(const float* __restrict__ in,
                            const float* __restrict__ W,
                            const float* __restrict__ bias,
                            const float* __restrict__ res,
                            const float* __restrict__ gamma,
                            const float* __restrict__ beta,
                            float* __restrict__ out) {
    __shared__ float sIn[64 * LD];
    __shared__ float sW[64 * LD];
    __shared__ int   sIsLast;
    const int row0 = blockIdx.x * 64;
    const int tx = threadIdx.x & 15;
    const int ty = threadIdx.x >> 4;

    float acc[4][4];
#pragma unroll
    for (int i = 0; i < 4; i++)
#pragma unroll
        for (int j = 0; j < 4; j++) acc[i][j] = 0.f;

#pragma unroll
    for (int i = threadIdx.x; i < 1024; i += 256) {
        int r = i >> 4, c4 = i & 15;
        int grow = row0 + r;
        float4 v = make_float4(0.f, 0.f, 0.f, 0.f);
        if (grow < NN) v = *(const float4*)&in[(size_t)grow * 64 + c4 * 4];
        *(float4*)&sIn[r * LD + c4 * 4] = v;
        *(float4*)&sW[r * LD + c4 * 4] = *(const float4*)&W[(size_t)r * 64 + c4 * 4];
    }
    __syncthreads();
#pragma unroll
    for (int k = 0; k < 64; k++) {
        float4 wv = *(const float4*)&sW[k * LD + tx * 4];
        float x0 = sIn[(ty * 4 + 0) * LD + k];
        float x1 = sIn[(ty * 4 + 1) * LD + k];
        float x2 = sIn[(ty * 4 + 2) * LD + k];
        float x3 = sIn[(ty * 4 + 3) * LD + k];
        acc[0][0] = fmaf(x0, wv.x, acc[0][0]); acc[0][1] = fmaf(x0, wv.y, acc[0][1]);
        acc[0][2] = fmaf(x0, wv.z, acc[0][2]); acc[0][3] = fmaf(x0, wv.w, acc[0][3]);
        acc[1][0] = fmaf(x1, wv.x, acc[1][0]); acc[1][1] = fmaf(x1, wv.y, acc[1][1]);
        acc[1][2] = fmaf(x1, wv.z, acc[1][2]); acc[1][3] = fmaf(x1, wv.w, acc[1][3]);
        acc[2][0] = fmaf(x2, wv.x, acc[2][0]); acc[2][1] = fmaf(x2, wv.y, acc[2][1]);
        acc[2][2] = fmaf(x2, wv.z, acc[2][2]); acc[2][3] = fmaf(x2, wv.w, acc[2][3]);
        acc[3][0] = fmaf(x3, wv.x, acc[3][0]); acc[3][1] = fmaf(x3, wv.y, acc[3][1]);
        acc[3][2] = fmaf(x3, wv.z, acc[3][2]); acc[3][3] = fmaf(x3, wv.w, acc[3][3]);
    }
    __syncthreads();

    float4 bv = *(const float4*)&bias[tx * 4];
    float s[4] = {0.f, 0.f, 0.f, 0.f};
    float q[4] = {0.f, 0.f, 0.f, 0.f};
#pragma unroll
    for (int r = 0; r < 4; r++) {
        int grow = row0 + ty * 4 + r;
        if (grow < NN) {
            float4 o;
            o.x = acc[r][0] + bv.x; o.y = acc[r][1] + bv.y;
            o.z = acc[r][2] + bv.z; o.w = acc[r][3] + bv.w;
            if (RES) {
                float4 rv = *(const float4*)&res[(size_t)grow * 64 + tx * 4];
                o.x += rv.x; o.y += rv.y; o.z += rv.z; o.w += rv.w;
            }
            *(float4*)&out[(size_t)grow * 64 + tx * 4] = o;
            if (STATS) {
                s[0] += o.x; q[0] = fmaf(o.x, o.x, q[0]);
                s[1] += o.y; q[1] = fmaf(o.y, o.y, q[1]);
                s[2] += o.z; q[2] = fmaf(o.z, o.z, q[2]);
                s[3] += o.w; q[3] = fmaf(o.w, o.w, q[3]);
            }
        }
    }
    if (STATS) {
        __syncthreads();   // done with sIn/sW; reuse for stats reduction
#pragma unroll
        for (int c = 0; c < 4; c++) {
            sIn[ty * 64 + tx * 4 + c] = s[c];
            sW [ty * 64 + tx * 4 + c] = q[c];
        }
        __syncthreads();
        if (threadIdx.x < 64) {
            float S = 0.f, Q = 0.f;
#pragma unroll
            for (int g2 = 0; g2 < 16; g2++) {
                S += sIn[g2 * 64 + threadIdx.x];
                Q += sW [g2 * 64 + threadIdx.x];
            }
            g_psum[blockIdx.x][threadIdx.x] = S;
            g_psq [blockIdx.x][threadIdx.x] = Q;
        }
        __syncthreads();

        // ---- last-block BN finalize (deterministic fixed-order reduce) ----
        if (threadIdx.x == 0) {
            __threadfence();
            unsigned old = atomicAdd(&g_done, 1u);
            sIsLast = (old == GBLK - 1) ? 1 : 0;
        }
        __syncthreads();
        if (sIsLast) {
            __threadfence();
            double* dS = (double*)sIn;   // reuse smem (each tile >= 2KB)
            double* dQ = (double*)sW;
            int col = threadIdx.x & 63, chunk = threadIdx.x >> 6;  // 4 chunks
            double S = 0.0, Q = 0.0;
            for (int b = chunk; b < GBLK; b += 4) {
                S += (double)g_psum[b][col];
                Q += (double)g_psq[b][col];
            }
            dS[threadIdx.x] = S; dQ[threadIdx.x] = Q;
            __syncthreads();
            if (threadIdx.x < 64) {
                int t = threadIdx.x;
                double SS = dS[t] + dS[64 + t] + dS[128 + t] + dS[192 + t];
                double QQ = dQ[t] + dQ[64 + t] + dQ[128 + t] + dQ[192 + t];
                double mu  = SS / (double)NN;
                double var = QQ / (double)NN - mu * mu;
                if (var < 0.0) var = 0.0;
                float inv = rsqrtf((float)var + 1e-5f);
                float a = gamma[t] * inv;
                g_aff_a[t] = a;
                g_aff_b[t] = fmaf(-(float)mu, a, beta[t]);
            }
            __syncthreads();
            if (threadIdx.x == 0) g_done = 0;   // reset for next layer / replay
        }
    }
}

// ---------------- predictor ----------------
__global__ void pred_kernel(const float* __restrict__ h,
                            const float* __restrict__ Wp,
                            const float* __restrict__ bp,
                            float* __restrict__ out) {
    __shared__ float sWp[DH * DOUT];
    __shared__ float sh2[8][DH];
    for (int i = threadIdx.x; i < DH * DOUT; i += 256) sWp[i] = Wp[i];
    __syncthreads();

    int warp = threadIdx.x >> 5;
    int lane = threadIdx.x & 31;
    int node = blockIdx.x * 8 + warp;
    if (node >= NN) return;

    int f = lane * 2;
    float2 hv = *(const float2*)&h[(size_t)node * DH + f];
    float v0 = fmaxf(fmaf(g_aff_a[f],     hv.x, g_aff_b[f]),     0.f);
    float v1 = fmaxf(fmaf(g_aff_a[f + 1], hv.y, g_aff_b[f + 1]), 0.f);
    sh2[warp][f]     = v0;
    sh2[warp][f + 1] = v1;
    __syncwarp();

    float acc0 = 0.f, acc1 = 0.f;
#pragma unroll
    for (int k = 0; k < DH; k++) {
        float t = sh2[warp][k];
        acc0 = fmaf(t, sWp[k * DOUT + lane], acc0);
        acc1 = fmaf(t, sWp[k * DOUT + 32 + (lane & 7)], acc1);
    }
    float l0 = acc0 + bp[lane];
    float l1 = acc1 + ((lane < 8) ? bp[32 + lane] : 0.f);

    float lm = l0;
    if (lane < 8) lm = fmaxf(lm, l1);
#pragma unroll
    for (int o = 16; o; o >>= 1) lm = fmaxf(lm, __shfl_xor_sync(0xffffffffu, lm, o));
    float se = __expf(l0 - lm) + ((lane < 8) ? __expf(l1 - lm) : 0.f);
#pragma unroll
    for (int o = 16; o; o >>= 1) se += __shfl_xor_sync(0xffffffffu, se, o);
    float lse = lm + logf(se);

    out[(size_t)node * DOUT + lane] = l0 - lse;
    if (lane < 8) out[(size_t)node * DOUT + 32 + lane] = l1 - lse;
}

// ---------------- launch ----------------
extern "C" void kernel_launch(void* const* d_in, const int* in_sizes, int n_in,
                              void* d_out, int out_size) {
    const float* x      = (const float*)d_in[0];
    const int*   ei     = (const int*)d_in[1];     // int32 (JAX x64 disabled)
    const float* W_enc  = (const float*)d_in[2];
    const float* b_enc  = (const float*)d_in[3];
    const float* Wg     = (const float*)d_in[4];
    const float* bg     = (const float*)d_in[5];
    const float* gamma  = (const float*)d_in[6];
    const float* beta   = (const float*)d_in[7];
    const float* W_pred = (const float*)d_in[8];
    const float* b_pred = (const float*)d_in[9];
    float*       out    = (float*)d_out;

    const int* srcp = ei;
    const int* dstp = ei + EE;

    float *bufA, *bufB, *bufU;
    cudaGetSymbolAddress((void**)&bufA, g_bufA);
    cudaGetSymbolAddress((void**)&bufB, g_bufB);
    cudaGetSymbolAddress((void**)&bufU, g_bufU);

    const int AGB = (NN / 2 + 7) / 8;            // agg blocks (8 warps, 2 nodes/warp)
    const int PB  = (NN + 7) / 8;                // pred blocks

    enccount_kernel<<<GBLK + EB, 256>>>(x, W_enc, b_enc, bufA, dstp);   // launch 1
    scan1_kernel<<<SCB, 256>>>();                                       // launch 2
    fillmsg_kernel<<<EB + MB, 256>>>(srcp, dstp, bufA);                 // launch 3

    // layer 0 (identity affine, no residual; gemm tail finalizes BN-0 affine)
    agg_kernel<<<AGB, 256>>>(bufA, bufU, 0);                            // launch 4 (profiled)
    gemm_kernel<false, true><<<GBLK, 256>>>(bufU, Wg, bg, nullptr,
                                            gamma, beta, bufB);

    float* h     = bufB;
    float* other = bufA;
    for (int l = 1; l < LL; l++) {
        msg_build_kernel<<<MB, 256>>>(h, 1);
        agg_kernel<<<AGB, 256>>>(h, bufU, 1);
        gemm_kernel<true, true><<<GBLK, 256>>>(bufU, Wg + (size_t)l * DH * DH,
                                               bg + (size_t)l * DH, h,
                                               gamma + (size_t)l * DH,
                                               beta + (size_t)l * DH, other);
        float* tmp = h; h = other; other = tmp;
    }

    // final BN affine was set by the last gemm's tail; predictor applies it
    pred_kernel<<<PB, 256>>>(h, W_pred, b_pred, out);
}

// round 16
// speedup vs baseline: 1.1046x; 1.1046x over previous
#include <cuda_runtime.h>
#include <cuda_fp16.h>
#include <math.h>

#define NN 100000
#define EE 1000000
#define DH 64
#define DIN 128
#define DOUT 40
#define LL 7
#define GBLK 1563      // ceil(NN/64)  (encoder)
#define GB2  782       // ceil(NN/128) (conv gemm)
#define SCB 391        // ceil(NN/256)
#define EB  3907       // ceil(EE/256)
#define MB  12500      // NN*32/256
#define LD 68          // padded smem row stride (floats)

// per-lane message packet: e = exp(m), m = relu(aff(h))+eps  (two features each)
struct __align__(8) Msg { __half2 e; __half2 m; };

// ---------------- scratch (static device memory; no allocs) ----------------
__device__ float    g_bufA[(size_t)NN * DH];
__device__ float    g_bufB[(size_t)NN * DH];
__device__ float    g_bufU[(size_t)NN * DH];
__device__ Msg      g_msg[(size_t)NN * 32];
__device__ int      g_counts[NN];
__device__ int      g_row_off[NN + 1];
__device__ int      g_cursor[NN];
__device__ int      g_csr_src[EE];
__device__ float    g_psum[GB2][DH];
__device__ float    g_psq[GB2][DH];
__device__ float    g_aff_a[DH];
__device__ float    g_aff_b[DH];
// decoupled-lookback scan state: high 32 bits status (0=invalid,1=agg,2=prefix), low 32 value
__device__ unsigned long long g_state[SCB];

// ---------------- fused: encoder GEMM + CSR count ----------------
__global__ void enccount_kernel(const float* __restrict__ in,
                                const float* __restrict__ W,
                                const float* __restrict__ bias,
                                float* __restrict__ out,
                                const int* __restrict__ dstp) {
    __shared__ float sIn[64 * LD];
    __shared__ float sW[64 * LD];
    if (blockIdx.x >= GBLK) {
        int i = (blockIdx.x - GBLK) * 256 + threadIdx.x;
        if (i < EE) atomicAdd(&g_counts[dstp[i]], 1);
        return;
    }
    const int row0 = blockIdx.x * 64;
    const int tx = threadIdx.x & 15;
    const int ty = threadIdx.x >> 4;

    float acc[4][4];
#pragma unroll
    for (int i = 0; i < 4; i++)
#pragma unroll
        for (int j = 0; j < 4; j++) acc[i][j] = 0.f;

    for (int kc = 0; kc < DIN; kc += 64) {
#pragma unroll
        for (int i = threadIdx.x; i < 1024; i += 256) {
            int r = i >> 4, c4 = i & 15;
            int grow = row0 + r;
            float4 v = make_float4(0.f, 0.f, 0.f, 0.f);
            if (grow < NN) v = *(const float4*)&in[(size_t)grow * DIN + kc + c4 * 4];
            *(float4*)&sIn[r * LD + c4 * 4] = v;
            *(float4*)&sW[r * LD + c4 * 4] = *(const float4*)&W[(size_t)(kc + r) * 64 + c4 * 4];
        }
        __syncthreads();
#pragma unroll
        for (int k = 0; k < 64; k++) {
            float4 wv = *(const float4*)&sW[k * LD + tx * 4];
            float x0 = sIn[(ty * 4 + 0) * LD + k];
            float x1 = sIn[(ty * 4 + 1) * LD + k];
            float x2 = sIn[(ty * 4 + 2) * LD + k];
            float x3 = sIn[(ty * 4 + 3) * LD + k];
            acc[0][0] = fmaf(x0, wv.x, acc[0][0]); acc[0][1] = fmaf(x0, wv.y, acc[0][1]);
            acc[0][2] = fmaf(x0, wv.z, acc[0][2]); acc[0][3] = fmaf(x0, wv.w, acc[0][3]);
            acc[1][0] = fmaf(x1, wv.x, acc[1][0]); acc[1][1] = fmaf(x1, wv.y, acc[1][1]);
            acc[1][2] = fmaf(x1, wv.z, acc[1][2]); acc[1][3] = fmaf(x1, wv.w, acc[1][3]);
            acc[2][0] = fmaf(x2, wv.x, acc[2][0]); acc[2][1] = fmaf(x2, wv.y, acc[2][1]);
            acc[2][2] = fmaf(x2, wv.z, acc[2][2]); acc[2][3] = fmaf(x2, wv.w, acc[2][3]);
            acc[3][0] = fmaf(x3, wv.x, acc[3][0]); acc[3][1] = fmaf(x3, wv.y, acc[3][1]);
            acc[3][2] = fmaf(x3, wv.z, acc[3][2]); acc[3][3] = fmaf(x3, wv.w, acc[3][3]);
        }
        __syncthreads();
    }

    float4 bv = *(const float4*)&bias[tx * 4];
#pragma unroll
    for (int r = 0; r < 4; r++) {
        int grow = row0 + ty * 4 + r;
        if (grow < NN) {
            float4 o;
            o.x = acc[r][0] + bv.x; o.y = acc[r][1] + bv.y;
            o.z = acc[r][2] + bv.z; o.w = acc[r][3] + bv.w;
            *(float4*)&out[(size_t)grow * 64 + tx * 4] = o;
        }
    }
}

// ---------------- single-pass decoupled-lookback scan ----------------
__global__ void scan1_kernel() {
    __shared__ int s[256];
    __shared__ int s_ex;
    const int b = blockIdx.x;
    const int tid = threadIdx.x;
    const int i = b * 256 + tid;
    int v = (i < NN) ? g_counts[i] : 0;
    s[tid] = v;
    __syncthreads();
#pragma unroll
    for (int d = 1; d < 256; d <<= 1) {
        int u = (tid >= d) ? s[tid - d] : 0;
        __syncthreads();
        s[tid] += u;
        __syncthreads();
    }
    int incl = s[tid];            // inclusive local prefix
    int total = s[255];

    if (tid == 0) {
        volatile unsigned long long* st = (volatile unsigned long long*)g_state;
        int ex = 0;
        if (b == 0) {
            __threadfence();
            st[0] = (2ULL << 32) | (unsigned)total;
        } else {
            __threadfence();
            st[b] = (1ULL << 32) | (unsigned)total;
            int j = b - 1;
            while (true) {
                unsigned long long q = st[j];
                unsigned status = (unsigned)(q >> 32);
                if (status == 2u) { ex += (int)(q & 0xffffffffu); break; }
                if (status == 1u) { ex += (int)(q & 0xffffffffu); j--; }
            }
            __threadfence();
            st[b] = (2ULL << 32) | (unsigned)(ex + total);
        }
        s_ex = ex;
    }
    __syncthreads();
    int base = s_ex;
    if (i < NN) {
        int off = base + incl - v;   // exclusive
        g_row_off[i] = off;
        g_cursor[i]  = off;
        g_counts[i]  = 0;            // ready for next replay
    }
    if (b == SCB - 1 && tid == 255) g_row_off[NN] = base + incl;
}

// ---- msg body: m = relu(aff(h)) + eps ; e = exp(m); both fp16 ----
__device__ __forceinline__ void msg_body(int i, const float* __restrict__ h, int use_aff) {
    int f = (i & 31) * 2;
    float a0 = 1.f, a1 = 1.f, b0 = 0.f, b1 = 0.f;
    if (use_aff) {
        a0 = g_aff_a[f]; a1 = g_aff_a[f + 1];
        b0 = g_aff_b[f]; b1 = g_aff_b[f + 1];
    }
    float2 v = ((const float2*)h)[i];
    float m0 = fmaxf(fmaf(a0, v.x, b0), 0.f) + 1e-7f;
    float m1 = fmaxf(fmaf(a1, v.y, b1), 0.f) + 1e-7f;
    Msg pk;
    pk.e = __floats2half2_rn(__expf(m0), __expf(m1));
    pk.m = __floats2half2_rn(m0, m1);
    g_msg[i] = pk;
}

// ---------------- fused: CSR fill + layer-0 msg build (+ scan state reset) ----------------
__global__ void fillmsg_kernel(const int* __restrict__ srcp,
                               const int* __restrict__ dstp,
                               const float* __restrict__ h) {
    if (blockIdx.x < EB) {
        if (blockIdx.x == 0) {
            for (int j = threadIdx.x; j < SCB; j += 256) g_state[j] = 0ULL;
        }
        int i = blockIdx.x * 256 + threadIdx.x;
        if (i < EE) {
            int d = dstp[i];
            int pos = atomicAdd(&g_cursor[d], 1);
            g_csr_src[pos] = srcp[i];
        }
    } else {
        int i = (blockIdx.x - EB) * 256 + threadIdx.x;
        if (i < NN * 32) msg_body(i, h, 0);
    }
}

__global__ void msg_build_kernel(const float* __restrict__ h, int use_aff) {
    int i = blockIdx.x * blockDim.x + threadIdx.x;
    if (i < NN * 32) msg_body(i, h, use_aff);
}

// ---------------- BN finalize ----------------
__global__ void finalize_kernel(const float* __restrict__ gamma,
                                const float* __restrict__ beta) {
    __shared__ double sS[1024], sQ[1024];
    int t = threadIdx.x;
    int col = t & 63, chunk = t >> 6;  // 16 chunks
    double S = 0.0, Q = 0.0;
    for (int b = chunk; b < GB2; b += 16) {
        S += (double)g_psum[b][col];
        Q += (double)g_psq[b][col];
    }
    sS[t] = S; sQ[t] = Q;
    __syncthreads();
    if (t < 64) {
        double SS = 0.0, QQ = 0.0;
#pragma unroll
        for (int g2 = 0; g2 < 16; g2++) { SS += sS[g2 * 64 + t]; QQ += sQ[g2 * 64 + t]; }
        double mu  = SS / (double)NN;
        double var = QQ / (double)NN - mu * mu;
        if (var < 0.0) var = 0.0;
        float inv = rsqrtf((float)var + 1e-5f);
        float a = gamma[t] * inv;
        g_aff_a[t] = a;
        g_aff_b[t] = fmaf(-(float)mu, a, beta[t]);
    }
}

// ---- one 4-edge gather batch: half2 in-batch accumulate, fp32 flush ----
__device__ __forceinline__ void batch4(int e, int lane,
                                       float& s0, float& s1, float& w0, float& w1) {
    int i0 = g_csr_src[e];
    int i1 = g_csr_src[e + 1];
    int i2 = g_csr_src[e + 2];
    int i3 = g_csr_src[e + 3];
    Msg p0 = g_msg[i0 * 32 + lane];
    Msg p1 = g_msg[i1 * 32 + lane];
    Msg p2 = g_msg[i2 * 32 + lane];
    Msg p3 = g_msg[i3 * 32 + lane];
    __half2 se = __hadd2(__hadd2(p0.e, p1.e), __hadd2(p2.e, p3.e));
    __half2 sw = __hfma2(p0.e, p0.m,
                 __hfma2(p1.e, p1.m,
                 __hfma2(p2.e, p2.m, __hmul2(p3.e, p3.m))));
    float2 fe = __half22float2(se);
    float2 fw = __half22float2(sw);
    s0 += fe.x; s1 += fe.y;
    w0 += fw.x; w1 += fw.y;
}

__device__ __forceinline__ void batch1(int e, int lane,
                                       float& s0, float& s1, float& w0, float& w1) {
    int i0 = g_csr_src[e];
    Msg p0 = g_msg[i0 * 32 + lane];
    float2 e0 = __half22float2(p0.e), m0 = __half22float2(p0.m);
    s0 += e0.x; s1 += e0.y;
    w0 = fmaf(e0.x, m0.x, w0);
    w1 = fmaf(e0.y, m0.y, w1);
}

// ---------------- GENConv aggregation: two nodes per warp, interleaved ----------------
__global__ void agg_kernel(const float* __restrict__ h,
                           float* __restrict__ u,
                           int use_aff) {
    int gw   = (blockIdx.x * blockDim.x + threadIdx.x) >> 5;
    int lane = threadIdx.x & 31;
    int n0 = gw * 2;
    if (n0 >= NN) return;
    int n1 = n0 + 1;
    int f = lane * 2;

    int p0 = g_row_off[n0], e0 = g_row_off[n0 + 1];
    int p1 = e0,            e1 = g_row_off[n1 + 1];

    float sA0 = 0.f, sA1 = 0.f, wA0 = 0.f, wA1 = 0.f;
    float sB0 = 0.f, sB1 = 0.f, wB0 = 0.f, wB1 = 0.f;

    while (p0 + 4 <= e0 && p1 + 4 <= e1) {
        batch4(p0, lane, sA0, sA1, wA0, wA1);
        batch4(p1, lane, sB0, sB1, wB0, wB1);
        p0 += 4; p1 += 4;
    }
    while (p0 + 4 <= e0) { batch4(p0, lane, sA0, sA1, wA0, wA1); p0 += 4; }
    while (p1 + 4 <= e1) { batch4(p1, lane, sB0, sB1, wB0, wB1); p1 += 4; }
    for (; p0 < e0; p0++) batch1(p0, lane, sA0, sA1, wA0, wA1);
    for (; p1 < e1; p1++) batch1(p1, lane, sB0, sB1, wB0, wB1);

    float a0 = 1.f, a1 = 1.f, b0 = 0.f, b1 = 0.f;
    if (use_aff) {
        a0 = g_aff_a[f]; a1 = g_aff_a[f + 1];
        b0 = g_aff_b[f]; b1 = g_aff_b[f + 1];
    }
    {
        float2 hn = *(const float2*)&h[(size_t)n0 * DH + f];
        float base0, base1;
        if (use_aff) {
            base0 = fmaxf(fmaf(a0, hn.x, b0), 0.f);
            base1 = fmaxf(fmaf(a1, hn.y, b1), 0.f);
        } else { base0 = hn.x; base1 = hn.y; }
        float2 o;
        o.x = base0 + ((sA0 > 0.f) ? wA0 / sA0 : 0.f);
        o.y = base1 + ((sA1 > 0.f) ? wA1 / sA1 : 0.f);
        *(float2*)&u[(size_t)n0 * DH + f] = o;
    }
    {
        float2 hn = *(const float2*)&h[(size_t)n1 * DH + f];
        float base0, base1;
        if (use_aff) {
            base0 = fmaxf(fmaf(a0, hn.x, b0), 0.f);
            base1 = fmaxf(fmaf(a1, hn.y, b1), 0.f);
        } else { base0 = hn.x; base1 = hn.y; }
        float2 o;
        o.x = base0 + ((sB0 > 0.f) ? wB0 / sB0 : 0.f);
        o.y = base1 + ((sB1 > 0.f) ? wB1 / sB1 : 0.f);
        *(float2*)&u[(size_t)n1 * DH + f] = o;
    }
}

// ---- conv GEMM: 128 rows/block, 8x4 per-thread tile; W via L1 (__ldg) ----
template <bool RES, bool STATS>
__global__ __launch_bounds__(256) void gemm_kernel(
        const float* __restrict__ in,
        const float* __restrict__ W,
        const float* __restrict__ bias,
        const float* __restrict__ res,
        float* __restrict__ out) {
    __shared__ float sIn[128 * LD];    // 34816 B < 48 KB
    const int row0 = blockIdx.x * 128;
    const int tx = threadIdx.x & 15;   // col group (4 cols)
    const int ty = threadIdx.x >> 4;   // row group (8 rows)

    float acc[8][4];
#pragma unroll
    for (int i = 0; i < 8; i++)
#pragma unroll
        for (int j = 0; j < 4; j++) acc[i][j] = 0.f;

#pragma unroll
    for (int i = threadIdx.x; i < 2048; i += 256) {
        int r = i >> 4, c4 = i & 15;
        int grow = row0 + r;
        float4 v = make_float4(0.f, 0.f, 0.f, 0.f);
        if (grow < NN) v = *(const float4*)&in[(size_t)grow * 64 + c4 * 4];
        *(float4*)&sIn[r * LD + c4 * 4] = v;
    }
    __syncthreads();
#pragma unroll
    for (int k = 0; k < 64; k++) {
        float4 wv = __ldg((const float4*)&W[(size_t)k * 64 + tx * 4]);
#pragma unroll
        for (int r = 0; r < 8; r++) {
            float x = sIn[(ty * 8 + r) * LD + k];
            acc[r][0] = fmaf(x, wv.x, acc[r][0]);
            acc[r][1] = fmaf(x, wv.y, acc[r][1]);
            acc[r][2] = fmaf(x, wv.z, acc[r][2]);
            acc[r][3] = fmaf(x, wv.w, acc[r][3]);
        }
    }
    __syncthreads();

    float4 bv = *(const float4*)&bias[tx * 4];
    float s[4] = {0.f, 0.f, 0.f, 0.f};
    float q[4] = {0.f, 0.f, 0.f, 0.f};
#pragma unroll
    for (int r = 0; r < 8; r++) {
        int grow = row0 + ty * 8 + r;
        if (grow < NN) {
            float4 o;
            o.x = acc[r][0] + bv.x; o.y = acc[r][1] + bv.y;
            o.z = acc[r][2] + bv.z; o.w = acc[r][3] + bv.w;
            if (RES) {
                float4 rv = *(const float4*)&res[(size_t)grow * 64 + tx * 4];
                o.x += rv.x; o.y += rv.y; o.z += rv.z; o.w += rv.w;
            }
            *(float4*)&out[(size_t)grow * 64 + tx * 4] = o;
            if (STATS) {
                s[0] += o.x; q[0] = fmaf(o.x, o.x, q[0]);
                s[1] += o.y; q[1] = fmaf(o.y, o.y, q[1]);
                s[2] += o.z; q[2] = fmaf(o.z, o.z, q[2]);
                s[3] += o.w; q[3] = fmaf(o.w, o.w, q[3]);
            }
        }
    }
    if (STATS) {
        __syncthreads();   // done reading sIn; reuse for stats (S at 0, Q at 2048)
#pragma unroll
        for (int c = 0; c < 4; c++) {
            sIn[ty * 64 + tx * 4 + c]        = s[c];
            sIn[2048 + ty * 64 + tx * 4 + c] = q[c];
        }
        __syncthreads();
        if (threadIdx.x < 64) {
            float S = 0.f, Q = 0.f;
#pragma unroll
            for (int g2 = 0; g2 < 16; g2++) {
                S += sIn[g2 * 64 + threadIdx.x];
                Q += sIn[2048 + g2 * 64 + threadIdx.x];
            }
            g_psum[blockIdx.x][threadIdx.x] = S;
            g_psq [blockIdx.x][threadIdx.x] = Q;
        }
    }
}

// ---------------- predictor ----------------
__global__ void pred_kernel(const float* __restrict__ h,
                            const float* __restrict__ Wp,
                            const float* __restrict__ bp,
                            float* __restrict__ out) {
    __shared__ float sWp[DH * DOUT];
    __shared__ float sh2[8][DH];
    for (int i = threadIdx.x; i < DH * DOUT; i += 256) sWp[i] = Wp[i];
    __syncthreads();

    int warp = threadIdx.x >> 5;
    int lane = threadIdx.x & 31;
    int node = blockIdx.x * 8 + warp;
    if (node >= NN) return;

    int f = lane * 2;
    float2 hv = *(const float2*)&h[(size_t)node * DH + f];
    float v0 = fmaxf(fmaf(g_aff_a[f],     hv.x, g_aff_b[f]),     0.f);
    float v1 = fmaxf(fmaf(g_aff_a[f + 1], hv.y, g_aff_b[f + 1]), 0.f);
    sh2[warp][f]     = v0;
    sh2[warp][f + 1] = v1;
    __syncwarp();

    float acc0 = 0.f, acc1 = 0.f;
#pragma unroll
    for (int k = 0; k < DH; k++) {
        float t = sh2[warp][k];
        acc0 = fmaf(t, sWp[k * DOUT + lane], acc0);
        acc1 = fmaf(t, sWp[k * DOUT + 32 + (lane & 7)], acc1);
    }
    float l0 = acc0 + bp[lane];
    float l1 = acc1 + ((lane < 8) ? bp[32 + lane] : 0.f);

    float lm = l0;
    if (lane < 8) lm = fmaxf(lm, l1);
#pragma unroll
    for (int o = 16; o; o >>= 1) lm = fmaxf(lm, __shfl_xor_sync(0xffffffffu, lm, o));
    float se = __expf(l0 - lm) + ((lane < 8) ? __expf(l1 - lm) : 0.f);
#pragma unroll
    for (int o = 16; o; o >>= 1) se += __shfl_xor_sync(0xffffffffu, se, o);
    float lse = lm + logf(se);

    out[(size_t)node * DOUT + lane] = l0 - lse;
    if (lane < 8) out[(size_t)node * DOUT + 32 + lane] = l1 - lse;
}

// ---------------- launch ----------------
extern "C" void kernel_launch(void* const* d_in, const int* in_sizes, int n_in,
                              void* d_out, int out_size) {
    const float* x      = (const float*)d_in[0];
    const int*   ei     = (const int*)d_in[1];     // int32 (JAX x64 disabled)
    const float* W_enc  = (const float*)d_in[2];
    const float* b_enc  = (const float*)d_in[3];
    const float* Wg     = (const float*)d_in[4];
    const float* bg     = (const float*)d_in[5];
    const float* gamma  = (const float*)d_in[6];
    const float* beta   = (const float*)d_in[7];
    const float* W_pred = (const float*)d_in[8];
    const float* b_pred = (const float*)d_in[9];
    float*       out    = (float*)d_out;

    const int* srcp = ei;
    const int* dstp = ei + EE;

    float *bufA, *bufB, *bufU;
    cudaGetSymbolAddress((void**)&bufA, g_bufA);
    cudaGetSymbolAddress((void**)&bufB, g_bufB);
    cudaGetSymbolAddress((void**)&bufU, g_bufU);

    const int AGB = (NN / 2 + 7) / 8;            // agg blocks (8 warps, 2 nodes/warp)
    const int PB  = (NN + 7) / 8;                // pred blocks

    enccount_kernel<<<GBLK + EB, 256>>>(x, W_enc, b_enc, bufA, dstp);   // launch 1
    scan1_kernel<<<SCB, 256>>>();                                       // launch 2
    fillmsg_kernel<<<EB + MB, 256>>>(srcp, dstp, bufA);                 // launch 3

    // layer 0 (identity affine, no residual; gemm collects stats for BN-0)
    agg_kernel<<<AGB, 256>>>(bufA, bufU, 0);                            // launch 4 (profiled)
    gemm_kernel<false, true><<<GB2, 256>>>(bufU, Wg, bg, nullptr, bufB);

    float* h     = bufB;
    float* other = bufA;
    for (int l = 1; l < LL; l++) {
        finalize_kernel<<<1, 1024>>>(gamma + (size_t)(l - 1) * DH, beta + (size_t)(l - 1) * DH);
        msg_build_kernel<<<MB, 256>>>(h, 1);
        agg_kernel<<<AGB, 256>>>(h, bufU, 1);
        gemm_kernel<true, true><<<GB2, 256>>>(bufU, Wg + (size_t)l * DH * DH,
                                              bg + (size_t)l * DH, h, other);
        float* tmp = h; h = other; other = tmp;
    }

    // final BN -> relu -> predictor -> log_softmax
    finalize_kernel<<<1, 1024>>>(gamma + (size_t)(LL - 1) * DH, beta + (size_t)(LL - 1) * DH);
    pred_kernel<<<PB, 256>>>(h, W_pred, b_pred, out);
}